// round 6
// baseline (speedup 1.0000x reference)
#include <cuda_runtime.h>
#include <cuda_bf16.h>
#include <cstdint>
#include <cstddef>

// Problem constants (fixed by the dataset).
#define Bn 64
#define Pn 512
#define Qn 64
#define Dn 512
#define H4n 1024
#define G3n 1536
#define NTF 512          // fused kernel threads
#define NTP 256          // precompute kernels threads

// ---------------- scratch (device globals; no allocations allowed) ----------
__device__ float g_aT[Qn * Bn * Dn];   // rows m=q*64+b
__device__ float g_bT[Pn * Bn * Dn];   // rows p*64+b
__device__ float g_qT[Dn * Qn * Bn];   // qT[e][q*64+b]
__device__ float g_h[2][Bn * Dn];
__device__ float g_c[Bn * Dn];
__device__ float g_ct[Bn * Dn];
__device__ float g_x[Bn * H4n];
__device__ float g_gi[Bn * G3n];
__device__ float g_gh[Bn * G3n];
// Wv split into bf16 hi/lo, plain row-major [n][k]
__device__ __nv_bfloat16 g_WvH[Dn * Dn];
__device__ __nv_bfloat16 g_WvL[Dn * Dn];

// ---------------- software grid barrier -------------------------------------
__device__ unsigned g_cnt = 0;
__device__ volatile unsigned g_gen = 0;

__device__ __forceinline__ void grid_sync(int G) {
    __syncthreads();
    if (threadIdx.x == 0) {
        __threadfence();
        unsigned gen = g_gen;
        unsigned old = atomicAdd(&g_cnt, 1);
        if (old == (unsigned)(G - 1)) {
            atomicExch(&g_cnt, 0u);
            __threadfence();
            g_gen = gen + 1;
        } else {
            while (g_gen == gen) { }
        }
        __threadfence();
    }
    __syncthreads();
}

// ---------------- PTX helpers ------------------------------------------------
__device__ __forceinline__ uint32_t s2u(const void* p) {
    uint32_t r;
    asm("{ .reg .u64 t; cvta.to.shared.u64 t, %1; cvt.u32.u64 %0, t; }"
        : "=r"(r) : "l"(p));
    return r;
}

__device__ __forceinline__ void ldsm4(uint32_t* r, uint32_t addr) {
    asm volatile("ldmatrix.sync.aligned.m8n8.x4.shared.b16 {%0,%1,%2,%3}, [%4];"
                 : "=r"(r[0]), "=r"(r[1]), "=r"(r[2]), "=r"(r[3]) : "r"(addr));
}

__device__ __forceinline__ void mma16816(float* d, const uint32_t* a,
                                         const uint32_t* b) {
    asm volatile(
        "mma.sync.aligned.m16n8k16.row.col.f32.bf16.bf16.f32 "
        "{%0,%1,%2,%3}, {%4,%5,%6,%7}, {%8,%9}, {%0,%1,%2,%3};"
        : "+f"(d[0]), "+f"(d[1]), "+f"(d[2]), "+f"(d[3])
        : "r"(a[0]), "r"(a[1]), "r"(a[2]), "r"(a[3]), "r"(b[0]), "r"(b[1]));
}

__device__ __forceinline__ float fast_tanh(float x) {
    float t = __expf(2.0f * x);
    return 1.0f - __fdividef(2.0f, t + 1.0f);
}

#define NB(id) asm volatile("bar.sync %0, 256;" :: "r"(id) : "memory")

#define REDADD(p, v) \
    asm volatile("red.global.add.f32 [%0], %1;" :: "l"(p), "f"(v) : "memory")

// ---------------- precompute: 128x128x8 SGEMM NT with output-row permutation
__global__ void __launch_bounds__(NTP) gemm128_nt(
    const float* __restrict__ A, const float* __restrict__ Bw,
    float* __restrict__ C, int M, int N, int K, int permInner)
{
    __shared__ float As[8][132];
    __shared__ float Bs[8][132];
    const int tid = threadIdx.x;
    const int bm = blockIdx.y, bn = blockIdx.x;
    const int lr = tid >> 1;
    const int lk = (tid & 1) * 4;
    const int tx = tid & 15, ty = tid >> 4;

    const float* Ab = A + (size_t)(bm * 128 + lr) * K + lk;
    const float* Bb = Bw + (size_t)(bn * 128 + lr) * K + lk;

    float acc[8][8];
#pragma unroll
    for (int i = 0; i < 8; i++)
#pragma unroll
        for (int j = 0; j < 8; j++) acc[i][j] = 0.0f;

    for (int k0 = 0; k0 < K; k0 += 8) {
        float4 av = *(const float4*)(Ab + k0);
        float4 bv = *(const float4*)(Bb + k0);
        __syncthreads();
        As[lk + 0][lr] = av.x; As[lk + 1][lr] = av.y;
        As[lk + 2][lr] = av.z; As[lk + 3][lr] = av.w;
        Bs[lk + 0][lr] = bv.x; Bs[lk + 1][lr] = bv.y;
        Bs[lk + 2][lr] = bv.z; Bs[lk + 3][lr] = bv.w;
        __syncthreads();
#pragma unroll
        for (int kk = 0; kk < 8; kk++) {
            float a[8], b[8];
            *(float4*)&a[0] = *(const float4*)&As[kk][ty * 4];
            *(float4*)&a[4] = *(const float4*)&As[kk][ty * 4 + 64];
            *(float4*)&b[0] = *(const float4*)&Bs[kk][tx * 4];
            *(float4*)&b[4] = *(const float4*)&Bs[kk][tx * 4 + 64];
#pragma unroll
            for (int i = 0; i < 8; i++)
#pragma unroll
                for (int j = 0; j < 8; j++)
                    acc[i][j] = fmaf(a[i], b[j], acc[i][j]);
        }
    }

    const int outer = M / permInner;
#pragma unroll
    for (int i = 0; i < 8; i++) {
        int rl = ty * 4 + ((i < 4) ? i : (60 + i));
        int m = bm * 128 + rl;
        int orow = (m % permInner) * outer + m / permInner;
        float* Crow = C + (size_t)orow * N + bn * 128;
        *(float4*)&Crow[tx * 4] =
            make_float4(acc[i][0], acc[i][1], acc[i][2], acc[i][3]);
        *(float4*)&Crow[tx * 4 + 64] =
            make_float4(acc[i][4], acc[i][5], acc[i][6], acc[i][7]);
    }
}

// ---------------- precompute: split Wv into bf16 hi/lo (row-major) ----------
__global__ void __launch_bounds__(NTP) split_wv(const float* __restrict__ Wv) {
    int idx = blockIdx.x * NTP + threadIdx.x;   // 512*512
    float v = Wv[idx];
    __nv_bfloat16 hi = __float2bfloat16(v);
    __nv_bfloat16 lo = __float2bfloat16(v - __bfloat162float(hi));
    g_WvH[idx] = hi;
    g_WvL[idx] = lo;
}

// ---------------- precompute: transpose question to qT[e][q*64+b] -----------
__global__ void __launch_bounds__(NTP) transpose_q(const float* __restrict__ question) {
    int idx = blockIdx.x * NTP + threadIdx.x;   // Dn*Qn*Bn
    int e = idx >> 12, r = idx & 4095;
    int q = r >> 6, b = r & 63;
    g_qT[idx] = question[((size_t)b * Qn + q) * Dn + e];
}

// ---------------- small-M GEMM tile (fp32 SIMT), 256-thread half -------------
// MODE 0: c = h@Wvp^T           MODE 1: x = sigmoid(pa@Wg^T)*pa
// MODE 2: gi = x@W_ih^T + b_ih  MODE 3: gh = h@W_hh^T + b_hh
template <int MODE>
__device__ void gemm64_tile(const float* __restrict__ A, const float* __restrict__ A2,
                            const float* __restrict__ W, const float* __restrict__ bias,
                            float* __restrict__ Cout, int N, int K, int strideA,
                            int n0, float* sh, int tid, int barid)
{
    float (*As)[68] = (float(*)[68])sh;             // [32][68]
    float (*Ws)[17] = (float(*)[17])(sh + 32 * 68); // [32][17]
    const int ar = tid >> 2, ak = (tid & 3) * 8;
    const int wr = tid >> 4, wk = (tid & 15) * 2;
    const int m0 = (tid & 15) * 4, n = tid >> 4;

    float acc[4] = {0.f, 0.f, 0.f, 0.f};

    for (int k0 = 0; k0 < K; k0 += 32) {
        float av[8];
        if (MODE == 1) {
#pragma unroll
            for (int j = 0; j < 8; j++) {
                int k = k0 + ak + j;
                av[j] = (k < 512) ? A[(size_t)ar * strideA + k]
                                  : A2[ar * 512 + (k - 512)];
            }
        } else {
            float4 v0 = *(const float4*)&A[(size_t)ar * K + k0 + ak];
            float4 v1 = *(const float4*)&A[(size_t)ar * K + k0 + ak + 4];
            av[0] = v0.x; av[1] = v0.y; av[2] = v0.z; av[3] = v0.w;
            av[4] = v1.x; av[5] = v1.y; av[6] = v1.z; av[7] = v1.w;
        }
        float wv0 = W[(size_t)(n0 + wr) * K + k0 + wk];
        float wv1 = W[(size_t)(n0 + wr) * K + k0 + wk + 1];
        NB(barid);
#pragma unroll
        for (int j = 0; j < 8; j++) As[ak + j][ar] = av[j];
        Ws[wk][wr] = wv0;
        Ws[wk + 1][wr] = wv1;
        NB(barid);
#pragma unroll
        for (int kk = 0; kk < 32; kk++) {
            float w = Ws[kk][n];
            float4 a = *(const float4*)&As[kk][m0];
            acc[0] = fmaf(a.x, w, acc[0]);
            acc[1] = fmaf(a.y, w, acc[1]);
            acc[2] = fmaf(a.z, w, acc[2]);
            acc[3] = fmaf(a.w, w, acc[3]);
        }
    }

    const int col = n0 + n;
#pragma unroll
    for (int i = 0; i < 4; i++) {
        int b = m0 + i;
        float v = acc[i];
        if (MODE == 1) {
            float pav = (col < 512) ? A[(size_t)b * strideA + col]
                                    : A2[b * 512 + (col - 512)];
            v = pav / (1.0f + __expf(-v));
        } else if (MODE == 2 || MODE == 3) {
            v += bias[col];
        }
        Cout[(size_t)b * N + col] = v;
    }
}

// ---------------- phase-B tile: mma + fused softmax/ct -----------------------
// smem: 2 buffers x (Ah, Al, Bh, Bl), each 128x40 b16 = 10240 B. total 81920 B.
// After mma, buffers reused as St[128][132] fp32 transpose stage (67584 B).
#define BSTR 40
#define BUFB 10240

__device__ __forceinline__ void fill_store(
    unsigned char* dsmp, int bufsel, uint32_t wrOff,
    const float4* pa, const float4* pb, const float4* pc,
    uint4 pwh, uint4 pwl)
{
    unsigned char* base = dsmp + bufsel * 4 * BUFB;
    const float* av = (const float*)pa;
    const float* bv = (const float*)pb;
    const float* cv = (const float*)pc;
    uint32_t hw[4], lw[4];
#pragma unroll
    for (int i = 0; i < 4; i++) {
        float t0 = fast_tanh(av[i * 2] + bv[i * 2] + cv[i * 2]);
        float t1 = fast_tanh(av[i * 2 + 1] + bv[i * 2 + 1] + cv[i * 2 + 1]);
        __nv_bfloat16 h0 = __float2bfloat16(t0);
        __nv_bfloat16 h1 = __float2bfloat16(t1);
        __nv_bfloat16 l0 = __float2bfloat16(t0 - __bfloat162float(h0));
        __nv_bfloat16 l1 = __float2bfloat16(t1 - __bfloat162float(h1));
        hw[i] = ((uint32_t)__bfloat16_as_ushort(h1) << 16) | __bfloat16_as_ushort(h0);
        lw[i] = ((uint32_t)__bfloat16_as_ushort(l1) << 16) | __bfloat16_as_ushort(l0);
    }
    *(uint4*)(base + wrOff)            = make_uint4(hw[0], hw[1], hw[2], hw[3]);
    *(uint4*)(base + BUFB + wrOff)     = make_uint4(lw[0], lw[1], lw[2], lw[3]);
    *(uint4*)(base + 2 * BUFB + wrOff) = pwh;
    *(uint4*)(base + 3 * BUFB + wrOff) = pwl;
}

__device__ void s_tile_mma(int tm, int tn, int p, unsigned char* dsmp, int tid,
                           int G) {
    const uint32_t sbase = s2u(dsmp);
    const int wid = tid >> 5, lane = tid & 31;
    const int wm = wid & 3, wn = wid >> 2;

    const int r = tid >> 2, sub = tid & 3;         // fill: row r, k-octet sub
    const int m = tm * 128 + r, bb = m & 63;
    const float* aP = g_aT + (size_t)m * Dn;
    const float* bP = g_bT + ((size_t)p * Bn + bb) * Dn;
    const float* cP = g_c + (size_t)bb * Dn;
    const __nv_bfloat16* wHp = g_WvH + (size_t)(tn * 128 + r) * Dn;
    const __nv_bfloat16* wLp = g_WvL + (size_t)(tn * 128 + r) * Dn;
    const uint32_t wrOff = (uint32_t)(r * BSTR + sub * 8) * 2;

    const uint32_t aOff =
        (uint32_t)(((wm * 32 + (lane & 15)) * BSTR + (lane >> 4) * 8) * 2);
    const uint32_t bOff =
        (uint32_t)(((wn * 32 + ((lane >> 3) & 2) * 4 + (lane & 7)) * BSTR +
                    ((lane >> 3) & 1) * 8) * 2);

    float4 pa[2], pb[2], pc[2];
    uint4 pwh, pwl;
    {   // chunk 0 load + store
        int kc = sub * 8;
        pa[0] = *(const float4*)(aP + kc); pa[1] = *(const float4*)(aP + kc + 4);
        pb[0] = *(const float4*)(bP + kc); pb[1] = *(const float4*)(bP + kc + 4);
        pc[0] = *(const float4*)(cP + kc); pc[1] = *(const float4*)(cP + kc + 4);
        pwh = *(const uint4*)(wHp + kc);   pwl = *(const uint4*)(wLp + kc);
        fill_store(dsmp, 0, wrOff, pa, pb, pc, pwh, pwl);
    }
    __syncthreads();

    float acc[2][4][4];
#pragma unroll
    for (int i = 0; i < 2; i++)
#pragma unroll
        for (int j = 0; j < 4; j++)
#pragma unroll
            for (int k = 0; k < 4; k++) acc[i][j][k] = 0.0f;

    for (int ch = 0; ch < 16; ch++) {
        if (ch < 15) {   // prefetch next chunk (LDG overlaps mma below)
            int kc = (ch + 1) * 32 + sub * 8;
            pa[0] = *(const float4*)(aP + kc); pa[1] = *(const float4*)(aP + kc + 4);
            pb[0] = *(const float4*)(bP + kc); pb[1] = *(const float4*)(bP + kc + 4);
            pc[0] = *(const float4*)(cP + kc); pc[1] = *(const float4*)(cP + kc + 4);
            pwh = *(const uint4*)(wHp + kc);   pwl = *(const uint4*)(wLp + kc);
        }
        const uint32_t sA = sbase + (uint32_t)(ch & 1) * 4 * BUFB;
#pragma unroll
        for (int ks = 0; ks < 2; ks++) {
            uint32_t ah[2][4], al[2][4], bh[2][4], bl[2][4];
#pragma unroll
            for (int mi = 0; mi < 2; mi++) {
                ldsm4(ah[mi], sA + aOff + mi * (16 * BSTR * 2) + ks * 32);
                ldsm4(al[mi], sA + BUFB + aOff + mi * (16 * BSTR * 2) + ks * 32);
            }
#pragma unroll
            for (int ng = 0; ng < 2; ng++) {
                ldsm4(bh[ng], sA + 2 * BUFB + bOff + ng * (16 * BSTR * 2) + ks * 32);
                ldsm4(bl[ng], sA + 3 * BUFB + bOff + ng * (16 * BSTR * 2) + ks * 32);
            }
#pragma unroll
            for (int mi = 0; mi < 2; mi++)
#pragma unroll
                for (int ni = 0; ni < 4; ni++) {
                    const int ng = ni >> 1, sb = ni & 1;
                    mma16816(acc[mi][ni], ah[mi], &bh[ng][sb * 2]);
                    mma16816(acc[mi][ni], ah[mi], &bl[ng][sb * 2]);
                    mma16816(acc[mi][ni], al[mi], &bh[ng][sb * 2]);
                }
        }
        if (ch < 15) {
            fill_store(dsmp, (ch + 1) & 1, wrOff, pa, pb, pc, pwh, pwl);
            __syncthreads();
        }
    }

    // ---- stage transposed tile St[e_local][m_local], stride 132 (no conflicts)
    __syncthreads();
    float* St = (float*)dsmp;
#pragma unroll
    for (int mi = 0; mi < 2; mi++) {
        const int row = wm * 32 + mi * 16 + (lane >> 2);
#pragma unroll
        for (int ni = 0; ni < 4; ni++) {
            const int col = wn * 32 + ni * 8 + (lane & 3) * 2;
            St[col * 132 + row]           = acc[mi][ni][0];
            St[(col + 1) * 132 + row]     = acc[mi][ni][1];
            St[col * 132 + row + 8]       = acc[mi][ni][2];
            St[(col + 1) * 132 + row + 8] = acc[mi][ni][3];
        }
    }
    __syncthreads();

    // ---- fused batch-softmax + c_t partials (warp-per-feature, shuffle-only)
    const int q0 = tm * 2;
#pragma unroll
    for (int pass = 0; pass < 8; pass++) {
        const int el = pass * 16 + wid;
        const float* Srow = St + el * 132;
        const int e = tn * 128 + el;
        float v00 = Srow[lane], v01 = Srow[lane + 32];
        float v10 = Srow[64 + lane], v11 = Srow[96 + lane];
        float m0 = fmaxf(v00, v01), m1 = fmaxf(v10, v11);
#pragma unroll
        for (int o = 16; o; o >>= 1) {
            m0 = fmaxf(m0, __shfl_xor_sync(0xFFFFFFFFu, m0, o));
            m1 = fmaxf(m1, __shfl_xor_sync(0xFFFFFFFFu, m1, o));
        }
        float e00 = __expf(v00 - m0), e01 = __expf(v01 - m0);
        float e10 = __expf(v10 - m1), e11 = __expf(v11 - m1);
        float s0 = e00 + e01, s1 = e10 + e11;
#pragma unroll
        for (int o = 16; o; o >>= 1) {
            s0 += __shfl_xor_sync(0xFFFFFFFFu, s0, o);
            s1 += __shfl_xor_sync(0xFFFFFFFFu, s1, o);
        }
        float i0 = 1.0f / s0, i1 = 1.0f / s1;
        const float* qe = g_qT + (size_t)e * 4096 + q0 * 64;
        float ct0 = e00 * i0 * qe[lane]      + e10 * i1 * qe[64 + lane];
        float ct1 = e01 * i0 * qe[lane + 32] + e11 * i1 * qe[96 + lane];
        REDADD(g_ct + (size_t)lane * Dn + e, ct0);
        REDADD(g_ct + (size_t)(lane + 32) * Dn + e, ct1);
    }
    __syncthreads();   // before next tile reuses buffers
    (void)G;
}

// ---------------- the persistent scan kernel --------------------------------
extern __shared__ unsigned char dsm[];

__global__ void __launch_bounds__(NTF) fused_scan(
    const float* __restrict__ passage,
    const float* __restrict__ Wvp, const float* __restrict__ Wg,
    const float* __restrict__ W_ih, const float* __restrict__ W_hh,
    const float* __restrict__ b_ih, const float* __restrict__ b_hh,
    float* __restrict__ out, int G)
{
    const int bid = blockIdx.x, tid = threadIdx.x;
    const int half = tid >> 8, htid = tid & 255, barid = 1 + half;
    float* shh = (float*)(dsm + half * 10880);

    // init h = 0
    for (int i = bid * NTF + tid; i < Bn * Dn; i += G * NTF) g_h[0][i] = 0.0f;
    grid_sync(G);

    for (int p = 0; p < Pn; p++) {
        const int cur = p & 1;
        const float* hcur = g_h[cur];

        // Phase A: zero ct; c = h@Wvp^T (32 jobs), gh = h@W_hh^T+b_hh (96 jobs)
        for (int i = bid * NTF + tid; i < Bn * Dn; i += G * NTF) g_ct[i] = 0.0f;
        for (int job = bid * 2 + half; job < 128; job += G * 2) {
            if (job < 32)
                gemm64_tile<0>(hcur, nullptr, Wvp, nullptr, g_c,
                               Dn, Dn, 0, job * 16, shh, htid, barid);
            else
                gemm64_tile<3>(hcur, nullptr, W_hh, b_hh, g_gh,
                               G3n, Dn, 0, (job - 32) * 16, shh, htid, barid);
        }
        grid_sync(G);

        // Phase B: S tiles (mma) + fused softmax/ct (128 tiles)
        for (int job = bid; job < 128; job += G)
            s_tile_mma(job >> 2, job & 3, p, dsm, tid, G);
        grid_sync(G);

        // Phase D: x = sigmoid(pa@Wg^T)*pa (64 jobs)
        for (int job = bid * 2 + half; job < 64; job += G * 2)
            gemm64_tile<1>(passage + (size_t)p * Dn, g_ct, Wg, nullptr, g_x,
                           H4n, H4n, Pn * Dn, job * 16, shh, htid, barid);
        grid_sync(G);

        // Phase E: gi = x@W_ih^T + b_ih (96 jobs)
        for (int job = bid * 2 + half; job < 96; job += G * 2)
            gemm64_tile<2>(g_x, nullptr, W_ih, b_ih, g_gi,
                           G3n, H4n, 0, job * 16, shh, htid, barid);
        grid_sync(G);

        // Phase F: GRU elementwise update + output write
        for (int i = bid * NTF + tid; i < Bn * Dn; i += G * NTF) {
            int b = i >> 9, d = i & 511;
            const float* gi = &g_gi[b * G3n];
            const float* gh = &g_gh[b * G3n];
            float r = 1.0f / (1.0f + __expf(-(gi[d] + gh[d])));
            float z = 1.0f / (1.0f + __expf(-(gi[512 + d] + gh[512 + d])));
            float nn = tanhf(gi[1024 + d] + r * gh[1024 + d]);
            float h = hcur[i];
            float hnew = (1.0f - z) * nn + z * h;
            g_h[cur ^ 1][i] = hnew;
            out[((size_t)b * Pn + p) * Dn + d] = hnew;
        }
        grid_sync(G);
    }
}

// ---------------- launch -----------------------------------------------------
#define FS_SMEM (8 * BUFB)   // 81920 bytes

extern "C" void kernel_launch(void* const* d_in, const int* in_sizes, int n_in,
                              void* d_out, int out_size) {
    (void)in_sizes; (void)n_in; (void)out_size;
    const float* passage  = (const float*)d_in[0];
    const float* question = (const float*)d_in[1];
    const float* Wuq  = (const float*)d_in[2];
    const float* Wup  = (const float*)d_in[3];
    const float* Wvp  = (const float*)d_in[4];
    const float* Wv   = (const float*)d_in[5];
    const float* Wg   = (const float*)d_in[6];
    const float* W_ih = (const float*)d_in[7];
    const float* W_hh = (const float*)d_in[8];
    const float* b_ih = (const float*)d_in[9];
    const float* b_hh = (const float*)d_in[10];
    float* out = (float*)d_out;

    void *p_aT, *p_bT;
    cudaGetSymbolAddress(&p_aT, g_aT);
    cudaGetSymbolAddress(&p_bT, g_bT);
    float* aT = (float*)p_aT;
    float* bT = (float*)p_bT;

    cudaFuncSetAttribute(fused_scan, cudaFuncAttributeMaxDynamicSharedMemorySize,
                         FS_SMEM);

    int G = 0;
    cudaDeviceGetAttribute(&G, cudaDevAttrMultiProcessorCount, 0);
    if (G <= 0) G = 148;

    // Precompute: aT rows q*64+b, bT rows p*64+b, Wv hi/lo split, question^T
    gemm128_nt<<<dim3(4, 32),  NTP>>>(question, Wuq, aT, Bn * Qn, Dn, Dn, Qn);
    gemm128_nt<<<dim3(4, 256), NTP>>>(passage,  Wup, bT, Bn * Pn, Dn, Dn, Pn);
    split_wv<<<(Dn * Dn) / NTP, NTP>>>(Wv);
    transpose_q<<<(Dn * Qn * Bn) / NTP, NTP>>>(question);

    // The whole 512-step scan in one persistent kernel.
    fused_scan<<<G, NTF, FS_SMEM>>>(passage, Wvp, Wg, W_ih, W_hh,
                                    b_ih, b_hh, out, G);
}